// round 9
// baseline (speedup 1.0000x reference)
#include <cuda_runtime.h>
#include <cstdint>

#define WW 128
#define HH 128
#define NP 2048
#define DIMU 768
#define PTOT (HH*WW)

// ---- scratch / sync (device globals: zero-init, restored each run) ----
__device__ __align__(16) float g_imr[PTOT];
__device__ __align__(16) float g_img[PTOT];
__device__ __align__(16) float g_imb[PTOT];
__device__ int g_flag[16];   // per 8-row band: # raster tiles done (0..8)
__device__ int g_done[16];   // per band: # consumer blocks passed (0..16)

// ---- packed f32x2 helpers (sm_103a FFMA2) ----
__device__ __forceinline__ unsigned long long pk2(float lo, float hi) {
    unsigned long long v;
    asm("mov.b64 %0, {%1, %2};" : "=l"(v) : "f"(lo), "f"(hi));
    return v;
}
__device__ __forceinline__ unsigned long long ffma2(unsigned long long a,
                                                    unsigned long long b,
                                                    unsigned long long c) {
    unsigned long long d;
    asm("fma.rn.f32x2 %0, %1, %2, %3;" : "=l"(d) : "l"(a), "l"(b), "l"(c));
    return d;
}

// ============================================================
// Single kernel, role-split blocks.
//  blocks 0..127 : raster a 16x8 px tile (R7 scheme), signal band
//  blocks 128..383: wait for band, project 48 dims x 1024 px
// All 384 blocks co-resident (occ 3/SM => capacity 444) so the
// flag spin cannot deadlock.
// ============================================================
__global__ __launch_bounds__(256, 3) void k_all(
    const float* __restrict__ xyz, const float* __restrict__ scaling,
    const float* __restrict__ rotation, const float* __restrict__ features,
    const float* __restrict__ opacity, const float* __restrict__ w_up,
    const float* __restrict__ b_up, float* __restrict__ out)
{
    const int tid = threadIdx.x;
    const int bid = blockIdx.x;

    if (bid < 128) {
        // ======================= RASTER ROLE =======================
        __shared__ __align__(16) float4 sA[2][256];   // gx, gy, 0.5A, B
        __shared__ __align__(16) float4 sB[2][256];   // 0.5C, op, cr, cg
        __shared__ __align__(16) float  scb[2][256];  // cb
        __shared__ int swc[2][8];

        const int lane = tid & 31;
        const int wid  = tid >> 5;

        const int x0 = (bid & 7) << 4;
        const int y0 = (bid >> 3) << 3;
        const int tx = tid & 15, ty = (tid >> 4) & 7;  // pixel for tid<128
        const float px = (float)(x0 + tx) + 0.5f;
        const float py = (float)(y0 + ty) + 0.5f;
        const float txmin = (float)x0 + 0.5f, txmax = (float)x0 + 15.5f;
        const float tymin = (float)y0 + 0.5f, tymax = (float)y0 + 7.5f;
        const bool rasterer = (tid < 128);

        float accr = 0.0f, accg = 0.0f, accb = 0.0f;

        // prefetch chunk 0
        float2 nxy = ((const float2*)xyz)[tid];
        float2 nsc = ((const float2*)scaling)[tid];
        float  nrt = rotation[tid];
        float  nop = opacity[tid];
        float  nf0 = features[3*tid + 0];
        float  nf1 = features[3*tid + 1];
        float  nf2 = features[3*tid + 2];

        #pragma unroll 1
        for (int ck = 0; ck < NP / 256; ck++) {
            const int c = ck & 1;
            float2 xy = nxy; float2 sc = nsc;
            float rt = nrt, op = nop, f0 = nf0, f1 = nf1, f2 = nf2;
            if (ck + 1 < NP / 256) {
                const int ngi = (ck + 1) * 256 + tid;
                nxy = ((const float2*)xyz)[ngi];
                nsc = ((const float2*)scaling)[ngi];
                nrt = rotation[ngi];
                nop = opacity[ngi];
                nf0 = features[3*ngi + 0];
                nf1 = features[3*ngi + 1];
                nf2 = features[3*ngi + 2];
            }

            // preprocess (fast intrinsics)
            float e0 = __expf(2.0f * xy.x);
            float e1 = __expf(2.0f * xy.y);
            float gx = __fdividef(128.0f * e0, e0 + 1.0f);  // 0.5*(tanh+1)*W
            float gy = __fdividef(128.0f * e1, e1 + 1.0f);
            float s0 = fabsf(sc.x + 0.5f);
            float s1 = fabsf(sc.y + 0.5f);
            float th = 6.283185307179586f *
                       __fdividef(1.0f, 1.0f + __expf(-rt));
            float sn, cs; __sincosf(th, &sn, &cs);
            float a = cs * s0, b = -sn * s1, dd = sn * s0, ee = cs * s1;
            float cxx = a*a + b*b;
            float cxy = a*dd + b*ee;
            float cyy = dd*dd + ee*ee;
            float det = cxx*cyy - cxy*cxy;
            float inv = __fdividef(1.0f, det);
            float hA =  0.5f * cyy * inv;
            float Bc = -cxy * inv;
            float hC =  0.5f * cxx * inv;
            float smax = __logf(255.0f * op);

            bool keep = false;
            if (det > 0.0f && smax > 0.0f) {
                float rx = sqrtf(2.0f * smax * cxx) * 1.001f + 0.02f;
                float ry = sqrtf(2.0f * smax * cyy) * 1.001f + 0.02f;
                keep = (gx + rx >= txmin) && (gx - rx <= txmax) &&
                       (gy + ry >= tymin) && (gy - ry <= tymax);
            }

            // deterministic ballot compaction (double-buffered)
            unsigned mask = __ballot_sync(0xffffffffu, keep);
            if (lane == 0) swc[c][wid] = __popc(mask);
            __syncthreads();
            int bp = 0, total = 0;
            #pragma unroll
            for (int w = 0; w < 8; w++) {
                int cw = swc[c][w];
                bp += (w < wid) ? cw : 0;
                total += cw;
            }
            if (keep) {
                int pos = bp + __popc(mask & ((1u << lane) - 1u));
                sA[c][pos]  = make_float4(gx, gy, hA, Bc);
                sB[c][pos]  = make_float4(hC, op, f0, f1);
                scb[c][pos] = f2;
            }
            __syncthreads();

            if (rasterer) {
                #pragma unroll 2
                for (int j = 0; j < total; j++) {
                    float4 a4 = sA[c][j];
                    float4 b4 = sB[c][j];
                    float  cb = scb[c][j];
                    float dx = a4.x - px;
                    float dy = a4.y - py;
                    float sig = a4.z * dx * dx + a4.w * dx * dy + b4.x * dy * dy;
                    float al = fminf(0.999f, b4.y * __expf(-sig));
                    al = (sig >= 0.0f && al >= (1.0f / 255.0f)) ? al : 0.0f;
                    accr = fmaf(al, b4.z, accr);
                    accg = fmaf(al, b4.w, accg);
                    accb = fmaf(al, cb,   accb);
                }
            }
        }

        if (rasterer) {
            const int p = (y0 + ty) * WW + (x0 + tx);
            g_imr[p] = fminf(1.0f, fmaxf(0.0f, accr));
            g_img[p] = fminf(1.0f, fmaxf(0.0f, accg));
            g_imb[p] = fminf(1.0f, fmaxf(0.0f, accb));
        }
        __threadfence();
        __syncthreads();
        if (tid == 0) atomicAdd(&g_flag[bid >> 3], 1);   // band done signal

    } else {
        // ====================== PROJECT ROLE =======================
        // block i = bid-128: band bx = i & 15, dim-group dg = i >> 4
        // pre-packed weights: [k][0]={wr2,wg2}, [k][1]={wb2,bias2}
        __shared__ __align__(16) ulonglong2 sw2[48][2];

        const int i  = bid - 128;
        const int bx = i & 15;
        const int d0 = (i >> 4) * 48;

        // stage weights while the raster band is still in flight
        if (tid < 48) {
            int d = d0 + tid;
            float wr = __ldg(&w_up[3*d + 0]);
            float wg = __ldg(&w_up[3*d + 1]);
            float wb = __ldg(&w_up[3*d + 2]);
            float bi = __ldg(&b_up[d]);
            ulonglong2 a; a.x = pk2(wr, wr); a.y = pk2(wg, wg);
            ulonglong2 b; b.x = pk2(wb, wb); b.y = pk2(bi, bi);
            sw2[tid][0] = a;
            sw2[tid][1] = b;
        }

        // wait for the 8 raster tiles of this band
        if (tid == 0) {
            while (atomicAdd(&g_flag[bx], 0) < 8) __nanosleep(64);
        }
        __syncthreads();
        __threadfence();

        const int p4 = bx * 256 + tid;               // float4 pixel index
        float4 R = ((const float4*)g_imr)[p4];
        float4 G = ((const float4*)g_img)[p4];
        float4 B = ((const float4*)g_imb)[p4];
        unsigned long long r01 = pk2(R.x, R.y), r23 = pk2(R.z, R.w);
        unsigned long long g01 = pk2(G.x, G.y), g23 = pk2(G.z, G.w);
        unsigned long long b01 = pk2(B.x, B.y), b23 = pk2(B.z, B.w);

        // last consumer of the band resets the flags (replay-safe)
        __syncthreads();
        if (tid == 0) {
            int v = atomicAdd(&g_done[bx], 1);
            if (v == 15) { g_done[bx] = 0; g_flag[bx] = 0; }
        }

        float* outp = out + (size_t)d0 * PTOT + (size_t)p4 * 4;
        #pragma unroll 6
        for (int k = 0; k < 48; k++) {
            ulonglong2 wa = sw2[k][0];     // {wr2, wg2}
            ulonglong2 wb = sw2[k][1];     // {wb2, bias2}
            unsigned long long vx =
                ffma2(b01, wb.x, ffma2(g01, wa.y, ffma2(r01, wa.x, wb.y)));
            unsigned long long vy =
                ffma2(b23, wb.x, ffma2(g23, wa.y, ffma2(r23, wa.x, wb.y)));
            float4 v;
            asm("mov.b64 {%0, %1}, %2;" : "=f"(v.x), "=f"(v.y) : "l"(vx));
            asm("mov.b64 {%0, %1}, %2;" : "=f"(v.z), "=f"(v.w) : "l"(vy));
            *(float4*)outp = v;
            outp += PTOT;
        }
    }
}

// ============================================================
extern "C" void kernel_launch(void* const* d_in, const int* in_sizes, int n_in,
                              void* d_out, int out_size) {
    // metadata order: x, xyz, scaling, rotation, features, opacity, w_up, b_up
    const float* xyz      = (const float*)d_in[1];
    const float* scaling  = (const float*)d_in[2];
    const float* rotation = (const float*)d_in[3];
    const float* features = (const float*)d_in[4];
    const float* opacity  = (const float*)d_in[5];
    const float* w_up     = (const float*)d_in[6];
    const float* b_up     = (const float*)d_in[7];
    float* out = (float*)d_out;

    k_all<<<384, 256>>>(xyz, scaling, rotation, features, opacity,
                        w_up, b_up, out);
}

// round 10
// speedup vs baseline: 1.2831x; 1.2831x over previous
#include <cuda_runtime.h>
#include <cstdint>

#define WW 128
#define HH 128
#define NP 2048
#define DIMU 768
#define PTOT (HH*WW)

// ---- packed f32x2 helpers (sm_103a FFMA2) ----
__device__ __forceinline__ unsigned long long pk2(float lo, float hi) {
    unsigned long long v;
    asm("mov.b64 %0, {%1, %2};" : "=l"(v) : "f"(lo), "f"(hi));
    return v;
}
__device__ __forceinline__ unsigned long long ffma2(unsigned long long a,
                                                    unsigned long long b,
                                                    unsigned long long c) {
    unsigned long long d;
    asm("fma.rn.f32x2 %0, %1, %2, %3;" : "=l"(d) : "l"(a), "l"(b), "l"(c));
    return d;
}

// ============================================================
// Single kernel, 256 independent blocks, 256 threads.
// Block = one 32x2-pixel tile. Phases (no inter-block deps):
//  0) stage all 768 packed weights into smem (24 KB)
//  1) 8 chunks: preprocess 256 gaussians (all threads, fast
//     MUFU), bbox-cull vs tile, ballot-compact (double-buffered);
//     threads 0..63 accumulate their pixel
//  2) pixels -> smem
//  3) each thread projects 48 dims for its 4-px group and does
//     48 coalesced STG.128 (per dim: 2x128B row segments)
// ============================================================
__global__ __launch_bounds__(256, 2) void k_one(
    const float* __restrict__ xyz, const float* __restrict__ scaling,
    const float* __restrict__ rotation, const float* __restrict__ features,
    const float* __restrict__ opacity, const float* __restrict__ w_up,
    const float* __restrict__ b_up, float* __restrict__ out)
{
    __shared__ __align__(16) ulonglong2 sw2[DIMU][2]; // {wr2,wg2},{wb2,bias2}
    __shared__ __align__(16) float4 sA[2][256];       // gx, gy, 0.5A, B
    __shared__ __align__(16) float4 sB[2][256];       // 0.5C, op, cr, cg
    __shared__ __align__(16) float  scb[2][256];      // cb
    __shared__ __align__(16) float  spr[64], spg[64], spb[64];
    __shared__ int swc[2][8];

    const int tid  = threadIdx.x;
    const int lane = tid & 31;
    const int wid  = tid >> 5;
    const int bid  = blockIdx.x;

    // ---- phase 0: pack weights into smem ----
    #pragma unroll
    for (int d = tid; d < DIMU; d += 256) {
        float wr = __ldg(&w_up[3*d + 0]);
        float wg = __ldg(&w_up[3*d + 1]);
        float wb = __ldg(&w_up[3*d + 2]);
        float bi = __ldg(&b_up[d]);
        ulonglong2 a; a.x = pk2(wr, wr); a.y = pk2(wg, wg);
        ulonglong2 b; b.x = pk2(wb, wb); b.y = pk2(bi, bi);
        sw2[d][0] = a;
        sw2[d][1] = b;
    }

    // ---- tile geometry: 32x2 px ----
    const int x0 = (bid & 3) << 5;        // 0,32,64,96
    const int y0 = (bid >> 2) << 1;       // 0..126 step 2
    const float px = (float)(x0 + (tid & 31)) + 0.5f;     // tid<64
    const float py = (float)(y0 + ((tid >> 5) & 1)) + 0.5f;
    const float txmin = (float)x0 + 0.5f, txmax = (float)x0 + 31.5f;
    const float tymin = (float)y0 + 0.5f, tymax = (float)y0 + 1.5f;
    const bool rasterer = (tid < 64);

    float accr = 0.0f, accg = 0.0f, accb = 0.0f;

    // ---- prefetch chunk 0 ----
    float2 nxy = ((const float2*)xyz)[tid];
    float2 nsc = ((const float2*)scaling)[tid];
    float  nrt = rotation[tid];
    float  nop = opacity[tid];
    float  nf0 = features[3*tid + 0];
    float  nf1 = features[3*tid + 1];
    float  nf2 = features[3*tid + 2];

    #pragma unroll 1
    for (int ck = 0; ck < NP / 256; ck++) {
        const int c = ck & 1;
        float2 xy = nxy; float2 sc = nsc;
        float rt = nrt, op = nop, f0 = nf0, f1 = nf1, f2 = nf2;
        if (ck + 1 < NP / 256) {
            const int ngi = (ck + 1) * 256 + tid;
            nxy = ((const float2*)xyz)[ngi];
            nsc = ((const float2*)scaling)[ngi];
            nrt = rotation[ngi];
            nop = opacity[ngi];
            nf0 = features[3*ngi + 0];
            nf1 = features[3*ngi + 1];
            nf2 = features[3*ngi + 2];
        }

        // ---- preprocess (fast intrinsics) ----
        float e0 = __expf(2.0f * xy.x);
        float e1 = __expf(2.0f * xy.y);
        float gx = __fdividef(128.0f * e0, e0 + 1.0f);   // 0.5*(tanh+1)*W
        float gy = __fdividef(128.0f * e1, e1 + 1.0f);
        float s0 = fabsf(sc.x + 0.5f);
        float s1 = fabsf(sc.y + 0.5f);
        float th = 6.283185307179586f *
                   __fdividef(1.0f, 1.0f + __expf(-rt));
        float sn, cs; __sincosf(th, &sn, &cs);
        float a = cs * s0, b = -sn * s1, dd = sn * s0, ee = cs * s1;
        float cxx = a*a + b*b;
        float cxy = a*dd + b*ee;
        float cyy = dd*dd + ee*ee;
        float det = cxx*cyy - cxy*cxy;
        float inv = __fdividef(1.0f, det);
        float hA =  0.5f * cyy * inv;
        float Bc = -cxy * inv;
        float hC =  0.5f * cxx * inv;
        float smax = __logf(255.0f * op);   // alpha>=1/255 <=> sigma<=smax

        bool keep = false;
        if (det > 0.0f && smax > 0.0f) {
            float rx = sqrtf(2.0f * smax * cxx) * 1.001f + 0.02f;
            float ry = sqrtf(2.0f * smax * cyy) * 1.001f + 0.02f;
            keep = (gx + rx >= txmin) && (gx - rx <= txmax) &&
                   (gy + ry >= tymin) && (gy - ry <= tymax);
        }

        // ---- deterministic ballot compaction (double-buffered) ----
        unsigned mask = __ballot_sync(0xffffffffu, keep);
        if (lane == 0) swc[c][wid] = __popc(mask);
        __syncthreads();
        int bp = 0, total = 0;
        #pragma unroll
        for (int w = 0; w < 8; w++) {
            int cw = swc[c][w];
            bp += (w < wid) ? cw : 0;
            total += cw;
        }
        if (keep) {
            int pos = bp + __popc(mask & ((1u << lane) - 1u));
            sA[c][pos]  = make_float4(gx, gy, hA, Bc);
            sB[c][pos]  = make_float4(hC, op, f0, f1);
            scb[c][pos] = f2;
        }
        __syncthreads();

        // ---- raster accumulate (pixel-owning threads only) ----
        if (rasterer) {
            #pragma unroll 2
            for (int j = 0; j < total; j++) {
                float4 a4 = sA[c][j];
                float4 b4 = sB[c][j];
                float  cb = scb[c][j];
                float dx = a4.x - px;
                float dy = a4.y - py;
                float sig = a4.z * dx * dx + a4.w * dx * dy + b4.x * dy * dy;
                float al = fminf(0.999f, b4.y * __expf(-sig));
                al = (sig >= 0.0f && al >= (1.0f / 255.0f)) ? al : 0.0f;
                accr = fmaf(al, b4.z, accr);
                accg = fmaf(al, b4.w, accg);
                accb = fmaf(al, cb,   accb);
            }
        }
    }

    // ---- phase 2: pixels -> smem ----
    if (rasterer) {
        spr[tid] = fminf(1.0f, fmaxf(0.0f, accr));
        spg[tid] = fminf(1.0f, fmaxf(0.0f, accg));
        spb[tid] = fminf(1.0f, fmaxf(0.0f, accb));
    }
    __syncthreads();

    // ---- phase 3: projection + stores ----
    // thread: pg = tid&15 (float4 pixel group), dg = tid>>4;
    // dims d = dg*48 + k (k<48). For a dim, 16 threads write
    // two 128B row segments.
    const int pg = tid & 15;
    const int dg = tid >> 4;
    const int prow = pg >> 3;            // 0..1
    const int pcol = pg & 7;             // 0..7 (float4 within row)

    float4 R = ((const float4*)spr)[pg];
    float4 G = ((const float4*)spg)[pg];
    float4 B = ((const float4*)spb)[pg];
    unsigned long long r01 = pk2(R.x, R.y), r23 = pk2(R.z, R.w);
    unsigned long long g01 = pk2(G.x, G.y), g23 = pk2(G.z, G.w);
    unsigned long long b01 = pk2(B.x, B.y), b23 = pk2(B.z, B.w);

    float4* out4 = (float4*)out;
    const int d0 = dg * 48;
    float4* outp = out4 + (size_t)d0 * (PTOT / 4)
                        + (size_t)(y0 + prow) * (WW / 4) + (x0 >> 2) + pcol;

    #pragma unroll 6
    for (int k = 0; k < 48; k++) {
        ulonglong2 wa = sw2[d0 + k][0];   // {wr2, wg2}
        ulonglong2 wb = sw2[d0 + k][1];   // {wb2, bias2}
        unsigned long long vx =
            ffma2(b01, wb.x, ffma2(g01, wa.y, ffma2(r01, wa.x, wb.y)));
        unsigned long long vy =
            ffma2(b23, wb.x, ffma2(g23, wa.y, ffma2(r23, wa.x, wb.y)));
        float4 v;
        asm("mov.b64 {%0, %1}, %2;" : "=f"(v.x), "=f"(v.y) : "l"(vx));
        asm("mov.b64 {%0, %1}, %2;" : "=f"(v.z), "=f"(v.w) : "l"(vy));
        *outp = v;
        outp += PTOT / 4;
    }
}

// ============================================================
extern "C" void kernel_launch(void* const* d_in, const int* in_sizes, int n_in,
                              void* d_out, int out_size) {
    // metadata order: x, xyz, scaling, rotation, features, opacity, w_up, b_up
    const float* xyz      = (const float*)d_in[1];
    const float* scaling  = (const float*)d_in[2];
    const float* rotation = (const float*)d_in[3];
    const float* features = (const float*)d_in[4];
    const float* opacity  = (const float*)d_in[5];
    const float* w_up     = (const float*)d_in[6];
    const float* b_up     = (const float*)d_in[7];
    float* out = (float*)d_out;

    k_one<<<256, 256>>>(xyz, scaling, rotation, features, opacity,
                        w_up, b_up, out);
}